// round 3
// baseline (speedup 1.0000x reference)
#include <cuda_runtime.h>
#include <cstdint>

// SpecialSpmmFinal: out[src[e], :] += edge_w[e, :] for e in [0, E)
// N=100000, E=3200000, F=16, fp32. src = edge[0] (first E ints of [2,E]).
//
// R2: 4 edges per thread. src read as int4 (one LDG.128 per 4 edges),
// edge_w rows streamed with evict-first hint, 4 independent load->RED
// chains per thread to keep the LTS queue saturated. Atomics are
// red.global.add.v4.f32 (fire-and-forget), destinations L2-resident.

#define N_NODES 100000
#define N_EDGES 3200000
#define FEAT 16
#define EDGES_PER_THREAD 4

// ---------------------------------------------------------------------------
// Zero the output (harness poisons d_out with 0xAA).
// ---------------------------------------------------------------------------
__global__ void zero_out_kernel(float4* __restrict__ out, int n4) {
    int i = blockIdx.x * blockDim.x + threadIdx.x;
    if (i < n4) out[i] = make_float4(0.f, 0.f, 0.f, 0.f);
}

// ---------------------------------------------------------------------------
// Scatter-add, 4 edges per thread.
// ---------------------------------------------------------------------------
__device__ __forceinline__ void red_add_v4(float* dst, float4 v) {
    asm volatile(
        "red.global.add.v4.f32 [%0], {%1, %2, %3, %4};"
        :: "l"(dst), "f"(v.x), "f"(v.y), "f"(v.z), "f"(v.w)
        : "memory");
}

__device__ __forceinline__ float4 ldcs4(const float4* p) {
    float4 v;
    asm volatile("ld.global.cs.v4.f32 {%0, %1, %2, %3}, [%4];"
                 : "=f"(v.x), "=f"(v.y), "=f"(v.z), "=f"(v.w)
                 : "l"(p));
    return v;
}

__global__ void __launch_bounds__(256)
scatter_add_kernel(const int4* __restrict__ src4,   // [E/4] int4 view of src
                   const float4* __restrict__ w,    // [E, 4] float4 view of [E,16]
                   float* __restrict__ out) {       // [N, 16] f32
    int t = blockIdx.x * blockDim.x + threadIdx.x;  // 0 .. E/4-1
    if (t >= N_EDGES / EDGES_PER_THREAD) return;

    int4 s4 = src4[t];
    int s[EDGES_PER_THREAD] = {s4.x, s4.y, s4.z, s4.w};

    const float4* base = w + (size_t)t * (EDGES_PER_THREAD * 4);

    // Load all 16 float4 first (max MLP), then fire all 16 REDs.
    float4 v[EDGES_PER_THREAD][4];
    #pragma unroll
    for (int i = 0; i < EDGES_PER_THREAD; ++i) {
        #pragma unroll
        for (int j = 0; j < 4; ++j) {
            v[i][j] = ldcs4(base + i * 4 + j);
        }
    }

    #pragma unroll
    for (int i = 0; i < EDGES_PER_THREAD; ++i) {
        float* dst = out + (size_t)s[i] * FEAT;
        #pragma unroll
        for (int j = 0; j < 4; ++j) {
            red_add_v4(dst + j * 4, v[i][j]);
        }
    }
}

// ---------------------------------------------------------------------------
// kernel_launch
// Inputs (metadata order): edge [2,E] int32, edge_w [E,16] f32, then scalars.
// ---------------------------------------------------------------------------
extern "C" void kernel_launch(void* const* d_in, const int* in_sizes, int n_in,
                              void* d_out, int out_size) {
    const int4*   src4   = (const int4*)d_in[0];    // edge[0] = first E ints
    const float4* edge_w = (const float4*)d_in[1];
    float*        out    = (float*)d_out;

    (void)in_sizes; (void)n_in; (void)out_size;

    {
        int n4 = N_NODES * FEAT / 4;                // 400000
        int threads = 256;
        int blocks = (n4 + threads - 1) / threads;
        zero_out_kernel<<<blocks, threads>>>((float4*)out, n4);
    }

    {
        int nthreads_total = N_EDGES / EDGES_PER_THREAD;  // 800000
        int threads = 256;
        int blocks = (nthreads_total + threads - 1) / threads;  // 3125
        scatter_add_kernel<<<blocks, threads>>>(src4, edge_w, out);
    }
}

// round 5
// speedup vs baseline: 1.5846x; 1.5846x over previous
#include <cuda_runtime.h>
#include <cstdint>

// SpecialSpmmFinal: out[src[e], :] += edge_w[e, :] for e in [0, E)
// N=100000, E=3200000, F=16, fp32.
//
// R3: TMA bulk-copy (cp.async.bulk -> SMEM) for edge_w + src so the L1tex/LSU
// path serves ONLY the red.global.add.v4.f32 scatter (12.8M random-line
// wavefronts, the irreducible cost). Double-buffered 256-edge chunks with
// mbarrier expect_tx pipeline.

#define N_NODES 100000
#define N_EDGES 3200000
#define FEAT 16

#define CHUNK 256                        // edges per chunk
#define NCHUNKS (N_EDGES / CHUNK)        // 12500 (exact)
#define W_BYTES (CHUNK * FEAT * 4)       // 16384
#define S_BYTES (CHUNK * 4)              // 1024
#define STAGE_BYTES (W_BYTES + S_BYTES)  // 17408
#define GRID_BLOCKS 888                  // 6 blocks/SM * 148 SMs

// ---------------------------------------------------------------------------
// Zero the output (harness poisons d_out with 0xAA).
// ---------------------------------------------------------------------------
__global__ void zero_out_kernel(float4* __restrict__ out, int n4) {
    int i = blockIdx.x * blockDim.x + threadIdx.x;
    if (i < n4) out[i] = make_float4(0.f, 0.f, 0.f, 0.f);
}

// ---------------------------------------------------------------------------
// PTX helpers
// ---------------------------------------------------------------------------
__device__ __forceinline__ void red_add_v4(float* dst, float4 v) {
    asm volatile(
        "red.global.add.v4.f32 [%0], {%1, %2, %3, %4};"
        :: "l"(dst), "f"(v.x), "f"(v.y), "f"(v.z), "f"(v.w)
        : "memory");
}

__device__ __forceinline__ uint32_t smem_u32(const void* p) {
    return (uint32_t)__cvta_generic_to_shared(p);
}

__device__ __forceinline__ void mbar_init(uint32_t mbar, uint32_t count) {
    asm volatile("mbarrier.init.shared.b64 [%0], %1;" :: "r"(mbar), "r"(count) : "memory");
}

__device__ __forceinline__ void mbar_expect_tx(uint32_t mbar, uint32_t bytes) {
    asm volatile("mbarrier.arrive.expect_tx.shared.b64 _, [%0], %1;"
                 :: "r"(mbar), "r"(bytes) : "memory");
}

__device__ __forceinline__ void bulk_g2s(uint32_t dst_smem, const void* src_gmem,
                                         uint32_t bytes, uint32_t mbar) {
    asm volatile(
        "cp.async.bulk.shared::cta.global.mbarrier::complete_tx::bytes "
        "[%0], [%1], %2, [%3];"
        :: "r"(dst_smem), "l"(src_gmem), "r"(bytes), "r"(mbar)
        : "memory");
}

__device__ __forceinline__ void mbar_wait(uint32_t mbar, uint32_t phase) {
    asm volatile(
        "{\n\t"
        ".reg .pred p;\n\t"
        "WAIT_%=:\n\t"
        "mbarrier.try_wait.parity.acquire.cta.shared::cta.b64 p, [%0], %1, 0x989680;\n\t"
        "@!p bra WAIT_%=;\n\t"
        "}"
        :: "r"(mbar), "r"(phase) : "memory");
}

// ---------------------------------------------------------------------------
// TMA-fed scatter-add. Each block grid-strides over 256-edge chunks;
// thread i handles edge i of the chunk: 4x LDS.128 + 4x RED.128.
// ---------------------------------------------------------------------------
__global__ void __launch_bounds__(256)
scatter_add_tma_kernel(const char* __restrict__ edge_w,  // [E,16] f32 bytes
                       const char* __restrict__ src,     // [E] i32 bytes (edge[0])
                       float* __restrict__ out) {        // [N,16] f32
    __shared__ alignas(128) unsigned char buf[2][STAGE_BYTES];
    __shared__ alignas(8) unsigned long long mbar_storage[2];

    const int tid = threadIdx.x;
    const uint32_t mbar[2] = { smem_u32(&mbar_storage[0]), smem_u32(&mbar_storage[1]) };

    if (tid == 0) {
        mbar_init(mbar[0], 1);
        mbar_init(mbar[1], 1);
        // Make mbarrier init visible to the async (TMA) proxy.
        asm volatile("fence.proxy.async.shared::cta;" ::: "memory");
    }
    __syncthreads();

    uint32_t phase[2] = {0, 0};
    int stage = 0;

    const int c0 = blockIdx.x;

    // Prefetch first chunk.
    if (c0 < NCHUNKS && tid == 0) {
        mbar_expect_tx(mbar[0], STAGE_BYTES);
        bulk_g2s(smem_u32(&buf[0][0]),        edge_w + (size_t)c0 * W_BYTES, W_BYTES, mbar[0]);
        bulk_g2s(smem_u32(&buf[0][W_BYTES]),  src    + (size_t)c0 * S_BYTES, S_BYTES, mbar[0]);
    }

    for (int c = c0; c < NCHUNKS; c += GRID_BLOCKS) {
        const int cn = c + GRID_BLOCKS;
        const int nxt = stage ^ 1;
        if (cn < NCHUNKS && tid == 0) {
            // Previous iteration's __syncthreads guarantees buf[nxt] is free.
            mbar_expect_tx(mbar[nxt], STAGE_BYTES);
            bulk_g2s(smem_u32(&buf[nxt][0]),       edge_w + (size_t)cn * W_BYTES, W_BYTES, mbar[nxt]);
            bulk_g2s(smem_u32(&buf[nxt][W_BYTES]), src    + (size_t)cn * S_BYTES, S_BYTES, mbar[nxt]);
        }

        // Wait for current chunk's data.
        mbar_wait(mbar[stage], phase[stage]);
        phase[stage] ^= 1;

        // Compute: one edge per thread.
        const float4* wrow = (const float4*)(&buf[stage][0]) + (size_t)tid * 4;
        const int s = ((const int*)(&buf[stage][W_BYTES]))[tid];
        float* dst = out + (size_t)s * FEAT;

        float4 v0 = wrow[0];
        float4 v1 = wrow[1];
        float4 v2 = wrow[2];
        float4 v3 = wrow[3];
        red_add_v4(dst + 0,  v0);
        red_add_v4(dst + 4,  v1);
        red_add_v4(dst + 8,  v2);
        red_add_v4(dst + 12, v3);

        __syncthreads();   // all reads of buf[stage] done before it is refilled
        stage = nxt;
    }
}

// ---------------------------------------------------------------------------
// kernel_launch
// Inputs (metadata order): edge [2,E] int32, edge_w [E,16] f32, then scalars.
// ---------------------------------------------------------------------------
extern "C" void kernel_launch(void* const* d_in, const int* in_sizes, int n_in,
                              void* d_out, int out_size) {
    const char* edge   = (const char*)d_in[0];   // src = first E ints
    const char* edge_w = (const char*)d_in[1];
    float*      out    = (float*)d_out;

    (void)in_sizes; (void)n_in; (void)out_size;

    {
        int n4 = N_NODES * FEAT / 4;             // 400000
        int threads = 256;
        int blocks = (n4 + threads - 1) / threads;
        zero_out_kernel<<<blocks, threads>>>((float4*)out, n4);
    }

    scatter_add_tma_kernel<<<GRID_BLOCKS, 256>>>(edge_w, edge, out);
}

// round 6
// speedup vs baseline: 1.7977x; 1.1345x over previous
#include <cuda_runtime.h>
#include <cstdint>

// SpecialSpmmFinal: out[src[e], :] += edge_w[e, :] for e in [0, E)
// N=100000, E=3200000, F=16, fp32. src = edge[0] (first E ints of [2,E]).
//
// R5: back to R1's winning shape (1 edge/thread, 26-40 regs, high occupancy),
// with the scheduling bug fixed: all 4 row loads issued before any RED
// (4-deep MLP per thread), REDs carry no "memory" clobber (fire-and-forget,
// nothing may serialize against them), edge_w read with evict-first (__ldcs)
// to keep the 6.4MB output hot in L2 for the atomics.

#define N_NODES 100000
#define N_EDGES 3200000
#define FEAT 16

// ---------------------------------------------------------------------------
// Zero the output (harness poisons d_out with 0xAA).
// ---------------------------------------------------------------------------
__global__ void zero_out_kernel(float4* __restrict__ out, int n4) {
    int i = blockIdx.x * blockDim.x + threadIdx.x;
    if (i < n4) out[i] = make_float4(0.f, 0.f, 0.f, 0.f);
}

// ---------------------------------------------------------------------------
// Fire-and-forget 16B float reduction. No "memory" clobber: the operands are
// all by-value and the destination is never read by this kernel, so the
// compiler is free to schedule loads around it.
// ---------------------------------------------------------------------------
__device__ __forceinline__ void red_add_v4(float* dst, float4 v) {
    asm volatile(
        "red.global.add.v4.f32 [%0], {%1, %2, %3, %4};"
        :: "l"(dst), "f"(v.x), "f"(v.y), "f"(v.z), "f"(v.w));
}

// Evict-first 128-bit load.
__device__ __forceinline__ float4 ldcs4(const float4* p) {
    float4 v;
    asm volatile("ld.global.cs.v4.f32 {%0, %1, %2, %3}, [%4];"
                 : "=f"(v.x), "=f"(v.y), "=f"(v.z), "=f"(v.w)
                 : "l"(p));
    return v;
}

// ---------------------------------------------------------------------------
// Scatter-add: one thread per edge. Load src + 4x float4 (independent, 5-deep
// MLP), then fire 4x RED.128.
// ---------------------------------------------------------------------------
__global__ void __launch_bounds__(256)
scatter_add_kernel(const int* __restrict__ src,
                   const float4* __restrict__ w,   // [E,4] float4 view of [E,16]
                   float* __restrict__ out) {      // [N,16] f32
    int e = blockIdx.x * blockDim.x + threadIdx.x;
    if (e >= N_EDGES) return;

    const float4* row = w + (size_t)e * 4;

    // Issue all loads up front — independent, so the LSU queue holds 5
    // outstanding requests per thread while the first completes.
    int s = src[e];
    float4 v0 = ldcs4(row + 0);
    float4 v1 = ldcs4(row + 1);
    float4 v2 = ldcs4(row + 2);
    float4 v3 = ldcs4(row + 3);

    float* dst = out + (size_t)s * FEAT;
    red_add_v4(dst + 0,  v0);
    red_add_v4(dst + 4,  v1);
    red_add_v4(dst + 8,  v2);
    red_add_v4(dst + 12, v3);
}

// ---------------------------------------------------------------------------
// kernel_launch
// Inputs (metadata order): edge [2,E] int32, edge_w [E,16] f32, then scalars.
// ---------------------------------------------------------------------------
extern "C" void kernel_launch(void* const* d_in, const int* in_sizes, int n_in,
                              void* d_out, int out_size) {
    const int*    src    = (const int*)d_in[0];     // edge[0] = first E ints
    const float4* edge_w = (const float4*)d_in[1];
    float*        out    = (float*)d_out;

    (void)in_sizes; (void)n_in; (void)out_size;

    {
        int n4 = N_NODES * FEAT / 4;                // 400000
        int threads = 256;
        int blocks = (n4 + threads - 1) / threads;
        zero_out_kernel<<<blocks, threads>>>((float4*)out, n4);
    }

    {
        int threads = 256;
        int blocks = (N_EDGES + threads - 1) / threads;  // 12500
        scatter_add_kernel<<<blocks, threads>>>(src, edge_w, out);
    }
}

// round 7
// speedup vs baseline: 2.9059x; 1.6164x over previous
#include <cuda_runtime.h>
#include <cstdint>

// SpecialSpmmFinal: out[src[e], :] += edge_w[e, :] for e in [0, E)
// N=100000, E=3200000, F=16, fp32. src = edge[0] (first E ints of [2,E]).
//
// R6: lane-transposed scatter. One thread per (edge, 16B piece): thread
// t -> edge t/4, piece t%4. A warp's RED.128 now covers 8 nodes x 64
// contiguous bytes (8 L1tex wavefronts) instead of 32 scattered 16B slices
// (32 wavefronts). 4x fewer atomic wavefronts; edge_w loads stay perfectly
// coalesced (512B contiguous per warp).

#define N_NODES 100000
#define N_EDGES 3200000
#define FEAT 16
#define NQUARTERS (N_EDGES * 4)   // 12.8M quarter-rows

// ---------------------------------------------------------------------------
// Zero the output (harness poisons d_out with 0xAA).
// ---------------------------------------------------------------------------
__global__ void zero_out_kernel(float4* __restrict__ out, int n4) {
    int i = blockIdx.x * blockDim.x + threadIdx.x;
    if (i < n4) out[i] = make_float4(0.f, 0.f, 0.f, 0.f);
}

// ---------------------------------------------------------------------------
// Fire-and-forget 16B float reduction (no "memory" clobber: dest is never
// read in this kernel; nothing may serialize against it).
// ---------------------------------------------------------------------------
__device__ __forceinline__ void red_add_v4(float* dst, float4 v) {
    asm volatile(
        "red.global.add.v4.f32 [%0], {%1, %2, %3, %4};"
        :: "l"(dst), "f"(v.x), "f"(v.y), "f"(v.z), "f"(v.w));
}

// Evict-first 128-bit load (edge_w is touch-once; keep out[] hot in L2).
__device__ __forceinline__ float4 ldcs4(const float4* p) {
    float4 v;
    asm volatile("ld.global.cs.v4.f32 {%0, %1, %2, %3}, [%4];"
                 : "=f"(v.x), "=f"(v.y), "=f"(v.z), "=f"(v.w)
                 : "l"(p));
    return v;
}

// ---------------------------------------------------------------------------
// Lane-transposed scatter-add: thread t handles edge t/4, 16B piece t%4.
//   load : w[t]                (float4; warp = 512 contiguous bytes)
//   index: src[t/4]            (4-lane broadcast, one sector per 8 edges)
//   RED  : out[s*16 + (t%4)*4] (warp = 8 nodes x 64 contiguous bytes)
// ---------------------------------------------------------------------------
__global__ void __launch_bounds__(256)
scatter_add_kernel(const int* __restrict__ src,
                   const float4* __restrict__ w,   // [E*4] float4 view of [E,16]
                   float* __restrict__ out) {      // [N,16] f32
    int t = blockIdx.x * blockDim.x + threadIdx.x;
    if (t >= NQUARTERS) return;

    int   e = t >> 2;
    int   j = t & 3;

    int    s = src[e];
    float4 v = ldcs4(w + t);

    red_add_v4(out + (size_t)s * FEAT + j * 4, v);
}

// ---------------------------------------------------------------------------
// kernel_launch
// Inputs (metadata order): edge [2,E] int32, edge_w [E,16] f32, then scalars.
// ---------------------------------------------------------------------------
extern "C" void kernel_launch(void* const* d_in, const int* in_sizes, int n_in,
                              void* d_out, int out_size) {
    const int*    src    = (const int*)d_in[0];     // edge[0] = first E ints
    const float4* edge_w = (const float4*)d_in[1];
    float*        out    = (float*)d_out;

    (void)in_sizes; (void)n_in; (void)out_size;

    {
        int n4 = N_NODES * FEAT / 4;                // 400000
        int threads = 256;
        int blocks = (n4 + threads - 1) / threads;
        zero_out_kernel<<<blocks, threads>>>((float4*)out, n4);
    }

    {
        int threads = 256;
        int blocks = (NQUARTERS + threads - 1) / threads;  // 50000
        scatter_add_kernel<<<blocks, threads>>>(src, edge_w, out);
    }
}

// round 8
// speedup vs baseline: 3.0211x; 1.0396x over previous
#include <cuda_runtime.h>
#include <cstdint>

// SpecialSpmmFinal: out[src[e], :] += edge_w[e, :] for e in [0, E)
// N=100000, E=3200000, F=16, fp32. src = edge[0] (first E ints of [2,E]).
//
// R7: lane-transposed scatter (R6 mapping: thread -> (edge, 16B piece), warp's
// RED.128 covers 8 nodes x 64B) with 2 quarter-pieces per thread to double
// per-thread MLP and halve launch/index overhead. All loads front-batched,
// REDs fire-and-forget.

#define N_NODES 100000
#define N_EDGES 3200000
#define FEAT 16
#define NQUARTERS (N_EDGES * 4)       // 12,800,000 quarter-rows
#define HALFQ (NQUARTERS / 2)         // 6,400,000

// ---------------------------------------------------------------------------
// Zero the output (harness poisons d_out with 0xAA).
// ---------------------------------------------------------------------------
__global__ void zero_out_kernel(float4* __restrict__ out, int n4) {
    int i = blockIdx.x * blockDim.x + threadIdx.x;
    if (i < n4) out[i] = make_float4(0.f, 0.f, 0.f, 0.f);
}

// ---------------------------------------------------------------------------
// Fire-and-forget 16B float reduction (no "memory" clobber: dest is never
// read in this kernel; nothing may serialize against it).
// ---------------------------------------------------------------------------
__device__ __forceinline__ void red_add_v4(float* dst, float4 v) {
    asm volatile(
        "red.global.add.v4.f32 [%0], {%1, %2, %3, %4};"
        :: "l"(dst), "f"(v.x), "f"(v.y), "f"(v.z), "f"(v.w));
}

// Evict-first 128-bit load (edge_w is touch-once; keep out[] hot in L2).
__device__ __forceinline__ float4 ldcs4(const float4* p) {
    float4 v;
    asm volatile("ld.global.cs.v4.f32 {%0, %1, %2, %3}, [%4];"
                 : "=f"(v.x), "=f"(v.y), "=f"(v.z), "=f"(v.w)
                 : "l"(p));
    return v;
}

// ---------------------------------------------------------------------------
// Lane-transposed scatter-add, 2 pieces per thread.
// Thread t handles quarter-rows t and t+HALFQ:
//   piece q: edge q/4, j = q%4
//   load : w[q]                 (float4; warp = 512 contiguous bytes)
//   index: src[q/4]             (4-lane broadcast)
//   RED  : out[s*16 + j*4]      (warp = 8 nodes x 64 contiguous bytes)
// ---------------------------------------------------------------------------
__global__ void __launch_bounds__(256)
scatter_add_kernel(const int* __restrict__ src,
                   const float4* __restrict__ w,   // [E*4] float4 view of [E,16]
                   float* __restrict__ out) {      // [N,16] f32
    int t = blockIdx.x * blockDim.x + threadIdx.x;
    if (t >= HALFQ) return;

    const int q0 = t;
    const int q1 = t + HALFQ;

    // Front-batch all 4 independent loads (2 idx + 2 data) -> deep LSU queue.
    int    s0 = src[q0 >> 2];
    int    s1 = src[q1 >> 2];
    float4 v0 = ldcs4(w + q0);
    float4 v1 = ldcs4(w + q1);

    red_add_v4(out + (size_t)s0 * FEAT + (q0 & 3) * 4, v0);
    red_add_v4(out + (size_t)s1 * FEAT + (q1 & 3) * 4, v1);
}

// ---------------------------------------------------------------------------
// kernel_launch
// Inputs (metadata order): edge [2,E] int32, edge_w [E,16] f32, then scalars.
// ---------------------------------------------------------------------------
extern "C" void kernel_launch(void* const* d_in, const int* in_sizes, int n_in,
                              void* d_out, int out_size) {
    const int*    src    = (const int*)d_in[0];     // edge[0] = first E ints
    const float4* edge_w = (const float4*)d_in[1];
    float*        out    = (float*)d_out;

    (void)in_sizes; (void)n_in; (void)out_size;

    {
        int n4 = N_NODES * FEAT / 4;                // 400000
        int threads = 512;
        int blocks = (n4 + threads - 1) / threads;  // 782
        zero_out_kernel<<<blocks, threads>>>((float4*)out, n4);
    }

    {
        int threads = 256;
        int blocks = (HALFQ + threads - 1) / threads;  // 25000
        scatter_add_kernel<<<blocks, threads>>>(src, edge_w, out);
    }
}